// round 16
// baseline (speedup 1.0000x reference)
#include <cuda_runtime.h>

#define NB 16            // batches
#define NP 4096          // points per cloud
#define NG 32            // grids: set(0=shape,1=template) * 16 + batch
#define GD 32            // cells per axis
#define NC (GD*GD*GD)    // 32768 cells per grid
#define HBOX 4.0f
#define INVH 4.0f        // 1/h
#define H    0.25f
#define QTHREADS 512
#define BLK_PER_PAIR 4   // 32 pairings * 4 = 128 query blocks
#define SMEM_BYTES (NC*4 + NP*16)   // 128KB table + 64KB points = 196608

__device__ unsigned int g_cnt[NG][NC];     // counts (reused as scatter cursors)
__device__ unsigned int g_start[NG][NC];   // exclusive starts
__device__ float4       g_pts[NG][NP];     // cell-sorted points

__device__ __forceinline__ int cellcoord(float v) {
    int c = (int)floorf((v + HBOX) * INVH);
    return min(GD - 1, max(0, c));
}

// ---- zero counters + output scalar ----
__global__ void k_zero(float* __restrict__ out) {
    int i = blockIdx.x * 1024 + threadIdx.x;     // 1024 x 1024 = NG*NC exactly
    if (i == 0) out[0] = 0.0f;
    ((unsigned int*)g_cnt)[i] = 0u;
}

// ---- histogram: one thread per point (131072 threads) ----
__global__ void k_hist(const float* __restrict__ shape, const float* __restrict__ tmpl) {
    int idx = blockIdx.x * 256 + threadIdx.x;    // [0, 2*NB*NP)
    int set = idx >> 16;                          // 65536 points per set
    int w   = idx & 65535;
    const float* p = (set ? tmpl : shape) + (size_t)w * 3;
    int cell = (cellcoord(p[2]) * GD + cellcoord(p[1])) * GD + cellcoord(p[0]);
    int g = set * NB + (w >> 12);
    atomicAdd(&g_cnt[g][cell], 1u);
}

// ---- exclusive scan per grid: 32 blocks x 1024 threads, 32 cells/thread ----
__global__ void k_scan() {
    __shared__ unsigned int s[1024];
    int g = blockIdx.x;
    int t = threadIdx.x;
    int base = t * 32;
    unsigned int c[32];
    unsigned int tot = 0;
#pragma unroll
    for (int i = 0; i < 32; i++) { c[i] = g_cnt[g][base + i]; tot += c[i]; }
    s[t] = tot;
    __syncthreads();
    for (int off = 1; off < 1024; off <<= 1) {
        unsigned int u = (t >= off) ? s[t - off] : 0u;
        __syncthreads();
        s[t] += u;
        __syncthreads();
    }
    unsigned int run = s[t] - tot;               // exclusive prefix
#pragma unroll
    for (int i = 0; i < 32; i++) {
        g_start[g][base + i] = run;
        run += c[i];
        g_cnt[g][base + i] = 0u;                 // reset as scatter cursor
    }
}

// ---- scatter points into cell-sorted order ----
__global__ void k_scatter(const float* __restrict__ shape, const float* __restrict__ tmpl) {
    int idx = blockIdx.x * 256 + threadIdx.x;
    int set = idx >> 16;
    int w   = idx & 65535;
    const float* p = (set ? tmpl : shape) + (size_t)w * 3;
    float x = p[0], y = p[1], z = p[2];
    int cell = (cellcoord(z) * GD + cellcoord(y)) * GD + cellcoord(x);
    int g = set * NB + (w >> 12);
    unsigned int slot = g_start[g][cell] + atomicAdd(&g_cnt[g][cell], 1u);
    g_pts[g][slot] = make_float4(x, y, z, 0.0f);
}

// scan a contiguous cell run [c0..c1] (same z,y row): points are contiguous
__device__ __forceinline__ void scan_run(const unsigned int* __restrict__ table,
                                         const float4* __restrict__ pts,
                                         int c0, int c1,
                                         float qx, float qy, float qz, float& best2) {
    unsigned int e0 = table[c0];
    unsigned int e1 = (c1 == c0) ? e0 : table[c1];
    unsigned int p  = e0 >> 16;
    unsigned int pe = (e1 >> 16) + (e1 & 0xFFFFu);
    for (; p < pe; ++p) {
        float4 tp = pts[p];
        float dx = qx - tp.x, dy = qy - tp.y, dz = qz - tp.z;
        best2 = fminf(best2, dx * dx + dy * dy + dz * dz);
    }
}

// ---- query: expanding-ring exact NN; block = (pairing, chunk) ----
// Queries are read from the CELL-SORTED copy of the query cloud (g_pts[qg]) so
// that warp lanes handle spatially adjacent points: near-identical ring trip
// counts (minimal divergence) and broadcast-friendly smem reads. The Chamfer
// sum is order-independent, so reordering queries is exact.
extern __shared__ unsigned char smem_raw[];

__global__ void __launch_bounds__(QTHREADS) k_query(float* __restrict__ out) {
    unsigned int* table = (unsigned int*)smem_raw;            // NC entries
    float4*       pts   = (float4*)(smem_raw + NC * 4);       // NP entries

    int pairing = blockIdx.x / BLK_PER_PAIR;   // dir*16 + b
    int chunk   = blockIdx.x % BLK_PER_PAIR;
    int dir = pairing >> 4;
    int b   = pairing & 15;
    int tg  = (dir == 0) ? (NB + b) : b;       // target grid
    int qg  = (dir == 0) ? b : (NB + b);       // query cloud (cell-sorted copy)
    int t = threadIdx.x;

    // stage target grid into smem
    for (int i = t; i < NC; i += QTHREADS)
        table[i] = (g_start[tg][i] << 16) | g_cnt[tg][i];
    for (int i = t; i < NP; i += QTHREADS)
        pts[i] = g_pts[tg][i];
    __syncthreads();

    float local = 0.0f;
#pragma unroll
    for (int qq = 0; qq < 2; qq++) {
        int qi = chunk * 1024 + qq * QTHREADS + t;            // 0..4095
        float4 q = g_pts[qg][qi];
        float qx = q.x, qy = q.y, qz = q.z;
        int cx = cellcoord(qx), cy = cellcoord(qy), cz = cellcoord(qz);
        // distance from q to the grid box (0 if inside) keeps the ring bound valid
        float ox = fmaxf(fabsf(qx) - HBOX, 0.0f);
        float oy = fmaxf(fabsf(qy) - HBOX, 0.0f);
        float oz = fmaxf(fabsf(qz) - HBOX, 0.0f);
        float e = sqrtf(ox * ox + oy * oy + oz * oz);

        float best2 = 1e30f;
        for (int k = 0; k < GD; k++) {
            if (k >= 1) {
                float lb = (float)(k - 1) * H - e;            // min dist to ring >= k
                if (lb > 0.0f && lb * lb > best2) break;
            }
            int x0 = max(cx - k, 0), x1 = min(cx + k, GD - 1);
            for (int dz = -k; dz <= k; dz++) {
                int z = cz + dz;
                if ((unsigned)z >= (unsigned)GD) continue;
                int edge_z = (dz == -k) | (dz == k);
                for (int dy = -k; dy <= k; dy++) {
                    int y = cy + dy;
                    if ((unsigned)y >= (unsigned)GD) continue;
                    int rowbase = (z * GD + y) * GD;
                    if (edge_z || dy == -k || dy == k) {
                        // full row at this ring: contiguous x run
                        scan_run(table, pts, rowbase + x0, rowbase + x1, qx, qy, qz, best2);
                    } else {
                        // interior row: only the two x = cx +/- k cells (skip OOB)
                        int xa = cx - k, xb = cx + k;
                        if (xa >= 0)  scan_run(table, pts, rowbase + xa, rowbase + xa, qx, qy, qz, best2);
                        if (xb < GD)  scan_run(table, pts, rowbase + xb, rowbase + xb, qx, qy, qz, best2);
                    }
                }
            }
        }
        local += sqrtf(best2);
    }

    // block reduction (reuse smem after sync)
    __syncthreads();
    float* red = (float*)smem_raw;
#pragma unroll
    for (int o = 16; o > 0; o >>= 1)
        local += __shfl_down_sync(0xFFFFFFFFu, local, o);
    if ((t & 31) == 0) red[t >> 5] = local;
    __syncthreads();
    if (t == 0) {
        float s = 0.0f;
#pragma unroll
        for (int w = 0; w < QTHREADS / 32; w++) s += red[w];
        atomicAdd(out, (0.01f / 16.0f) * s);   // WEIGHT * mean over batch
    }
}

extern "C" void kernel_launch(void* const* d_in, const int* in_sizes, int n_in,
                              void* d_out, int out_size) {
    const float* shape = (const float*)d_in[0];
    const float* tmpl  = (const float*)d_in[1];
    float* out = (float*)d_out;

    cudaFuncSetAttribute(k_query, cudaFuncAttributeMaxDynamicSharedMemorySize, SMEM_BYTES);

    k_zero<<<1024, 1024>>>(out);
    k_hist<<<512, 256>>>(shape, tmpl);
    k_scan<<<NG, 1024>>>();
    k_scatter<<<512, 256>>>(shape, tmpl);
    k_query<<<NG * BLK_PER_PAIR, QTHREADS, SMEM_BYTES>>>(out);
}

// round 17
// speedup vs baseline: 3.0765x; 3.0765x over previous
#include <cuda_runtime.h>

#define NB 16
#define NP 4096
#define THREADS 256
#define TI 4                      // shape points per thread
#define ITILE (THREADS*TI)        // 1024
#define NITILE (NP/ITILE)         // 4
#define NJQ 4                     // j quarters
#define JQ (NP/NJQ)               // 1024 targets per CTA -> 16KB smem

// min d^2 as float-bits (non-negative -> unsigned-orderable)
// side 0: per shape point (min over tmpl); side 1: per tmpl point (min over shape)
__device__ unsigned int g_min[2][NB][NP];

__global__ void k_init(float* __restrict__ out) {
    int i = blockIdx.x * 1024 + threadIdx.x;   // 128 x 1024 = 2*16*4096 exactly
    if (i == 0) out[0] = 0.0f;
    ((unsigned int*)g_min)[i] = 0x7F800000u;   // +inf
}

// CTA = (i-tile, j-quarter, batch). One pass computes both direction mins.
__global__ void __launch_bounds__(THREADS) k_sym(const float* __restrict__ shape,
                                                 const float* __restrict__ tmpl) {
    __shared__ float4 sj[JQ];     // (tx,ty,tz,t2) 16KB

    const int itile = blockIdx.x;     // 0..3
    const int jq    = blockIdx.y;     // 0..3
    const int b     = blockIdx.z;     // 0..15
    const int t     = threadIdx.x;
    const int lane  = t & 31;

    const float* sp = shape + (size_t)b * NP * 3;
    const float* tp = tmpl  + ((size_t)b * NP + (size_t)jq * JQ) * 3;

    // stage j-quarter, computing |t|^2 on the fly
    for (int j = t; j < JQ; j += THREADS) {
        float x = tp[3*j], y = tp[3*j+1], z = tp[3*j+2];
        sj[j] = make_float4(x, y, z, x*x + y*y + z*z);
    }

    // per-thread shape points: (-2x,-2y,-2z, |p|^2)
    float sx[TI], sy[TI], sz[TI], p2[TI], rowm[TI];
#pragma unroll
    for (int k = 0; k < TI; k++) {
        int i = itile * ITILE + k * THREADS + t;
        float x = sp[3*i], y = sp[3*i+1], z = sp[3*i+2];
        p2[k] = x*x + y*y + z*z;
        sx[k] = -2.0f*x; sy[k] = -2.0f*y; sz[k] = -2.0f*z;
        rowm[k] = 1e30f;
    }
    __syncthreads();

    unsigned int* colg = &g_min[1][b][jq * JQ];

    for (int j = 0; j < JQ; ++j) {
        float4 tj = sj[j];                      // broadcast LDS.128
        float colp = 1e30f;
#pragma unroll
        for (int k = 0; k < TI; k++) {
            float c = fmaf(sz[k], tj.z, tj.w);  // t2 - 2pz*tz
            c = fmaf(sy[k], tj.y, c);
            c = fmaf(sx[k], tj.x, c);
            float d2 = c + p2[k];               // exact d^2 (same form as reference)
            rowm[k] = fminf(rowm[k], d2);
            colp    = fminf(colp, d2);
        }
        colp = fmaxf(colp, 0.0f);               // keep float-bits unsigned-orderable
        unsigned int u = __reduce_min_sync(0xFFFFFFFFu, __float_as_uint(colp));
        if (lane == 0) atomicMin(&colg[j], u);  // REDG.MIN, fire-and-forget
    }

    // flush row mins (partial over this j-quarter)
    unsigned int* rowg = &g_min[0][b][0];
#pragma unroll
    for (int k = 0; k < TI; k++) {
        int i = itile * ITILE + k * THREADS + t;
        atomicMin(&rowg[i], __float_as_uint(fmaxf(rowm[k], 0.0f)));
    }
}

// sqrt + sum + scale
__global__ void k_final(float* __restrict__ out) {
    __shared__ float warpsum[8];
    int idx = blockIdx.x * 256 + threadIdx.x;   // 512 x 256 = 131072
    unsigned int u = ((const unsigned int*)g_min)[idx];
    float v = sqrtf(__uint_as_float(u));        // stored values already >= 0

#pragma unroll
    for (int o = 16; o > 0; o >>= 1)
        v += __shfl_down_sync(0xFFFFFFFFu, v, o);
    int t = threadIdx.x;
    if ((t & 31) == 0) warpsum[t >> 5] = v;
    __syncthreads();
    if (t == 0) {
        float s = 0.0f;
#pragma unroll
        for (int w = 0; w < 8; w++) s += warpsum[w];
        atomicAdd(out, (0.01f / 16.0f) * s);    // WEIGHT * mean over batch
    }
}

extern "C" void kernel_launch(void* const* d_in, const int* in_sizes, int n_in,
                              void* d_out, int out_size) {
    const float* shape = (const float*)d_in[0];
    const float* tmpl  = (const float*)d_in[1];
    float* out = (float*)d_out;

    k_init<<<128, 1024>>>(out);
    dim3 g(NITILE, NJQ, NB);                    // 4 x 4 x 16 = 256 CTAs
    k_sym<<<g, THREADS>>>(shape, tmpl);
    k_final<<<512, 256>>>(out);
}